// round 16
// baseline (speedup 1.0000x reference)
#include <cuda_runtime.h>
#include <cuda_fp16.h>
#include <math.h>
#include <stdint.h>

#define BATCH 4096
#define T 25
#define CT 32
#define FIN 800
#define GO 64
#define H 256
#define VE 16
#define VR 12
#define KE 400
#define KR 300
#define KPE 448
#define KPR 320
#define NCHE 7
#define NCH 12
#define MT 32
#define NTHR 512
#define ES 260
#define NTASK 104
#define B_ERR_OFS (256 * KPE)
#define B_TOT (256 * KPE + 256 * KPR)
#define XRS 1552          /* X row stride bytes: 768 halfs + 16B pad */
#define SM_MAIN 66560     /* max(32*1552=49664, 2*32*260*4=66560) */

// ---------------- device scratch ----------------
__device__ float g_U[4][T * GO];
__device__ float g_S[4][GO];
__device__ int   g_ctr;
__device__ __align__(16) __half g_Bf[B_TOT];   // [n][K_pad] fp16, ecc then err
__device__ float g_C[2][H];

// ---------------- helpers ----------------
__device__ __forceinline__ void mma16816(float* d, uint32_t a0, uint32_t a1,
                                         uint32_t a2, uint32_t a3,
                                         uint32_t b0, uint32_t b1) {
    asm volatile(
        "mma.sync.aligned.m16n8k16.row.col.f32.f16.f16.f32 "
        "{%0,%1,%2,%3}, {%4,%5,%6,%7}, {%8,%9}, {%0,%1,%2,%3};"
        : "+f"(d[0]), "+f"(d[1]), "+f"(d[2]), "+f"(d[3])
        : "r"(a0), "r"(a1), "r"(a2), "r"(a3), "r"(b0), "r"(b1));
}
__device__ __forceinline__ void ldsm4(uint32_t* r, uint32_t addr) {
    asm volatile(
        "ldmatrix.sync.aligned.m8n8.x4.shared.b16 {%0,%1,%2,%3}, [%4];"
        : "=r"(r[0]), "=r"(r[1]), "=r"(r[2]), "=r"(r[3])
        : "r"(addr));
}
__device__ __forceinline__ uint32_t pack_h2(__half lo, __half hi) {
    return ((uint32_t)__half_as_ushort(hi) << 16) |
           (uint32_t)__half_as_ushort(lo);
}
__device__ __forceinline__ uint32_t smem_u32(const void* p) {
    uint32_t a;
    asm("{ .reg .u64 t; cvta.to.shared.u64 t, %1; cvt.u32.u64 %0, t; }"
        : "=r"(a) : "l"(p));
    return a;
}

// ===== fused precompute: U/S tasks + spin-sync + B + C (R15-proven) =====
__global__ void __launch_bounds__(256) k_pre2(
    const float* __restrict__ Pe, const float* __restrict__ Pr,
    const float* __restrict__ pbe, const float* __restrict__ pbr,
    const float* __restrict__ chbe, const float* __restrict__ chbr,
    const float* __restrict__ cwe, const float* __restrict__ cbe,
    const float* __restrict__ cwr, const float* __restrict__ cbr,
    const float* __restrict__ Wche, const float* __restrict__ Wchr,
    const int* __restrict__ eie, int Ee, const int* __restrict__ eir, int Er) {
    __shared__ float sP[64 * 64];
    __shared__ float sQ[64 * 64];
    __shared__ float sU0[T * GO];
    __shared__ float sU1[T * GO];
    __shared__ float swe[64];
    __shared__ float sws[16];
    const int tid = threadIdx.x;
    const int b = blockIdx.x;
    const int o = tid & 63;
    const int cc = tid >> 6;
    float* red = sQ;

    if (b < 100) {
        const int mat = b / T, tp = b % T;
        const int branch = mat >> 1, which = mat & 1;
        const float* cw = branch ? cwr : cwe;
        const float* W = (branch ? Wchr : Wche) + which * FIN * GO;
        float acc = 0.f;
#pragma unroll
        for (int k = 0; k < 3; k++) {
            int t = tp - k + 1;
            if (t >= 0 && t < T) {
#pragma unroll
                for (int cj = 0; cj < 8; cj++) {
                    int c = cc * 8 + cj;
                    acc += cw[c * 3 + k] * W[(c * T + t) * GO + o];
                }
            }
        }
        red[tid] = acc;
        __syncthreads();
        if (tid < 64)
            g_U[mat][tp * GO + tid] =
                red[tid] + red[64 + tid] + red[128 + tid] + red[192 + tid];
        __syncthreads();
        __threadfence();
        if (tid == 0) atomicAdd(&g_ctr, 1);
    } else if (b < 104) {
        const int mat = b - 100;
        const int branch = mat >> 1, which = mat & 1;
        const float* cb = branch ? cbr : cbe;
        const float* W = (branch ? Wchr : Wche) + which * FIN * GO;
        float acc = 0.f;
#pragma unroll
        for (int cj = 0; cj < 8; cj++) {
            int c = cc * 8 + cj;
            float s = 0.f;
#pragma unroll
            for (int t = 0; t < T; t++) s += W[(c * T + t) * GO + o];
            acc += cb[c] * s;
        }
        red[tid] = acc;
        __syncthreads();
        if (tid < 64)
            g_S[mat][tid] =
                red[tid] + red[64 + tid] + red[128 + tid] + red[192 + tid];
        __syncthreads();
        __threadfence();
        if (tid == 0) atomicAdd(&g_ctr, 1);
    }

    if (b < (VE + VR) * 4) {
        const int vb = b >> 2, hb = (b & 3) * 64;
        const int br = vb >= VE;
        const int v = br ? vb - VE : vb;
        const float* P = br ? Pr : Pe;
        const int* ei = br ? eir : eie;
        const int E = br ? Er : Ee;
        const size_t base = br ? (size_t)B_ERR_OFS : 0;
        const int KP = br ? KPR : KPE;

        if (tid < E) {
            int s = ei[tid], d = ei[E + tid];
            int degs = 0, degd = 0;
            for (int i = 0; i < E; i++) {
                int si = ei[i];
                degs += (si == s);
                degd += (si == d);
            }
            float ds = degs > 0 ? rsqrtf((float)degs) : 0.f;
            float dd = degd > 0 ? rsqrtf((float)degd) : 0.f;
            swe[tid] = -ds * dd;
        }
        __syncthreads();
        int cnt = 0;
        int nd[4] = {0, 0, 0, 0};
        float nw[4] = {0.f, 0.f, 0.f, 0.f};
        for (int e = 0; e < E; e++) {
            if (ei[e] == v && cnt < 4) {
                nd[cnt] = ei[E + e];
                nw[cnt] = swe[e];
                cnt++;
            }
        }

        for (int i4 = tid; i4 < 1024; i4 += 256) {
            int oo = i4 >> 4, hl4 = (i4 & 15) * 4;
            ((float4*)sP)[i4] = *(const float4*)&P[(v * GO + oo) * H + hb + hl4];
            float4 q = make_float4(0.f, 0.f, 0.f, 0.f);
#pragma unroll
            for (int j = 0; j < 4; j++) {
                if (j < cnt) {
                    float4 pd = *(const float4*)&P[(nd[j] * GO + oo) * H + hb + hl4];
                    q.x += nw[j] * pd.x;
                    q.y += nw[j] * pd.y;
                    q.z += nw[j] * pd.z;
                    q.w += nw[j] * pd.w;
                }
            }
            ((float4*)sQ)[i4] = q;
        }

        if (tid == 0) {
            while (atomicAdd(&g_ctr, 0) < NTASK) {
            }
        }
        __syncthreads();
        __threadfence();
        {
            const float4* U0 = (const float4*)g_U[2 * br];
            const float4* U1 = (const float4*)g_U[2 * br + 1];
            for (int i = tid; i < T * GO / 4; i += 256) {
                ((float4*)sU0)[i] = U0[i];
                ((float4*)sU1)[i] = U1[i];
            }
        }
        __syncthreads();

        const int hl4 = (tid & 15) * 4;
        const int tpg = tid >> 4;
        for (int tp = tpg; tp < T; tp += 16) {
            float4 acc = make_float4(0.f, 0.f, 0.f, 0.f);
#pragma unroll 16
            for (int oo = 0; oo < 64; oo++) {
                float4 p = *(const float4*)&sP[oo * 64 + hl4];
                float4 q = *(const float4*)&sQ[oo * 64 + hl4];
                float u0 = sU0[tp * GO + oo];
                float u1 = sU1[tp * GO + oo];
                acc.x += u0 * p.x + u1 * q.x;
                acc.y += u0 * p.y + u1 * q.y;
                acc.z += u0 * p.z + u1 * q.z;
                acc.w += u0 * p.w + u1 * q.w;
            }
            const int kg = v * T + tp;
            float vals[4] = {acc.x, acc.y, acc.z, acc.w};
#pragma unroll
            for (int j = 0; j < 4; j++) {
                int n = hb + hl4 + j;
                g_Bf[base + (size_t)n * KP + kg] = __float2half_rn(vals[j]);
            }
        }
    } else if (b < (VE + VR) * 4 + 16) {
        const int cb = b - (VE + VR) * 4;
        const int br = cb >> 3;
        const int hc = cb & 7;
        const float* chb = br ? chbr : chbe;
        const float* pb = br ? pbr : pbe;
        const float* P = br ? Pr : Pe;
        const int* ei = br ? eir : eie;
        const int E = br ? Er : Ee;
        const int V = br ? VR : VE;
        float* cfo = sP;
        float* s1v = sP + 64;
        float* red2 = sP + 160;

        if (tid < E) {
            int s = ei[tid], d = ei[E + tid];
            int degs = 0, degd = 0;
            for (int i = 0; i < E; i++) {
                int si = ei[i];
                degs += (si == s);
                degd += (si == d);
            }
            float ds = degs > 0 ? rsqrtf((float)degs) : 0.f;
            float dd = degd > 0 ? rsqrtf((float)degd) : 0.f;
            swe[tid] = -ds * dd;
        }
        __syncthreads();
        if (tid < 16) {
            float ws = 0.f;
            if (tid < V)
                for (int e = 0; e < E; e++)
                    if (ei[E + e] == tid) ws += swe[e];
            sws[tid] = ws;
        }

        if (tid == 0) {
            while (atomicAdd(&g_ctr, 0) < NTASK) {
            }
        }
        __syncthreads();
        __threadfence();
        if (tid < 64) {
            cfo[tid] = chb[tid] + g_S[2 * br][tid];
            s1v[tid] = g_S[2 * br + 1][tid];
        }
        __syncthreads();

        const int lane = tid & 31, rp = tid >> 5;
        const int h = hc * 32 + lane;
        const int R = V * GO;
        const int RP = R >> 3;
        float acc = 0.f;
#pragma unroll 4
        for (int r = rp * RP; r < (rp + 1) * RP; r++) {
            int oo = r & 63, v = r >> 6;
            float coef = cfo[oo] + s1v[oo] * sws[v];
            acc += coef * P[r * H + h];
        }
        red2[tid] = acc;
        __syncthreads();
        if (tid < 32) {
            float s = pb[h];
#pragma unroll
            for (int j = 0; j < 8; j++) s += red2[j * 32 + lane];
            g_C[br][h] = s;
        }
    } else {
        const int NE = 256 * (KPE - KE);
        const int NR = 256 * (KPR - KR);
        __half z = __float2half_rn(0.f);
        for (int i = tid; i < NE + NR; i += 256) {
            size_t idx;
            if (i < NE) {
                int n = i / (KPE - KE), k = KE + i % (KPE - KE);
                idx = (size_t)n * KPE + k;
            } else {
                int r = i - NE;
                int n = r / (KPR - KR), k = KR + r % (KPR - KR);
                idx = (size_t)B_ERR_OFS + (size_t)n * KPR + k;
            }
            g_Bf[idx] = z;
        }
    }
}

// ------- main: barrier-free HMMA mainloop; X staged once; B direct from L2 ----
extern __shared__ char smx[];

__global__ void __launch_bounds__(NTHR, 1)
k_main(const float* __restrict__ ecc, const float* __restrict__ err,
       const float* __restrict__ attnW, const float* __restrict__ attnb,
       const float* __restrict__ fc2W, const float* __restrict__ fc2b,
       float* __restrict__ out) {
    const int tid = threadIdx.x;
    const int wid = tid >> 5;       // 0..15
    const int lane = tid & 31;
    const int g = lane >> 2;
    const int i2 = (lane & 3) * 2;
    const int ns = wid * 16;        // warp's 16-col n slice
    const int rb = blockIdx.x * MT;

    if (blockIdx.x == 0 && tid == 0) g_ctr = 0;   // reset spin ctr (stream-ordered)

    // ---- stage ALL X once: 32 rows x 768 padded k-halfs ----
    // row layout: [0,448) ecc (zero >=400), [448,768) err (zero >=300)
#pragma unroll
    for (int it = 0; it < 12; it++) {
        int u = tid + it * NTHR;
        int row = u / 192, q = u % 192;
        int kg = q * 4;
        float4 x = make_float4(0.f, 0.f, 0.f, 0.f);
        if (kg < KPE) {
            if (kg < KE) x = *(const float4*)&ecc[(size_t)(rb + row) * KE + kg];
        } else {
            int k = kg - KPE;
            if (k < KR) x = *(const float4*)&err[(size_t)(rb + row) * KR + k];
        }
        *(uint2*)(smx + row * XRS + q * 8) =
            make_uint2(pack_h2(__float2half_rn(x.x), __float2half_rn(x.y)),
                       pack_h2(__float2half_rn(x.z), __float2half_rn(x.w)));
    }
    __syncthreads();

    // per-lane fragment bases
    const uint32_t suX = smem_u32(smx);
    const uint32_t arow = (uint32_t)(((lane & 7) + (lane & 8)) * XRS +
                                     (lane >> 4) * 16);
    const char* bbe =
        (const char*)g_Bf + ((size_t)(ns + g) * KPE + (lane & 3) * 2) * 2;
    const char* bbr = (const char*)(g_Bf + B_ERR_OFS) +
                      ((size_t)(ns + g) * KPR + (lane & 3) * 2) * 2;

    float de[2][2][4], dr[2][2][4];
#pragma unroll
    for (int mt = 0; mt < 2; mt++)
#pragma unroll
        for (int nt = 0; nt < 2; nt++)
#pragma unroll
            for (int j = 0; j < 4; j++) {
                de[mt][nt][j] = 0.f;
                dr[mt][nt][j] = 0.f;
            }

    // ---- barrier-free mainloop over 12 chunks ----
#pragma unroll
    for (int c = 0; c < NCH; c++) {
        const int br = (c >= NCHE);
        float (*d)[2][4] = br ? dr : de;
        const int KP = br ? KPR : KPE;
        const char* bb = br ? (bbr + (c - NCHE) * 128) : (bbe + c * 128);
        const uint32_t xoff = suX + arow + (uint32_t)(c * 128);
#pragma unroll
        for (int ks = 0; ks < 4; ks++) {
            uint32_t aa[2][4];
            ldsm4(aa[0], xoff + ks * 32);
            ldsm4(aa[1], xoff + 16 * XRS + ks * 32);
#pragma unroll
            for (int nt = 0; nt < 2; nt++) {
                const char* bp = bb + (size_t)nt * 8 * KP * 2 + ks * 32;
                uint32_t b0 = *(const uint32_t*)bp;
                uint32_t b1 = *(const uint32_t*)(bp + 16);
#pragma unroll
                for (int mt = 0; mt < 2; mt++)
                    mma16816(d[mt][nt], aa[mt][0], aa[mt][1], aa[mt][2],
                             aa[mt][3], b0, b1);
            }
        }
    }
    __syncthreads();   // all warps done reading sX before overwrite

    // -------- write fragments to smem (reuse X buffer) --------
    float* eg = (float*)smx;
    float* rg = eg + MT * ES;
#pragma unroll
    for (int mt = 0; mt < 2; mt++)
#pragma unroll
        for (int nt = 0; nt < 2; nt++) {
            int row = mt * 16 + g;
            int col = ns + nt * 8 + i2;
            eg[row * ES + col] = de[mt][nt][0];
            eg[row * ES + col + 1] = de[mt][nt][1];
            eg[(row + 8) * ES + col] = de[mt][nt][2];
            eg[(row + 8) * ES + col + 1] = de[mt][nt][3];
            rg[row * ES + col] = dr[mt][nt][0];
            rg[row * ES + col + 1] = dr[mt][nt][1];
            rg[(row + 8) * ES + col] = dr[mt][nt][2];
            rg[(row + 8) * ES + col + 1] = dr[mt][nt][3];
        }
    __syncthreads();

    // -------- gated tail: 1 warp per 2 rows --------
    const float attnb_v = attnb[0];
    const float fc2b_v = fc2b[0];
    for (int r = wid * 2; r < wid * 2 + 2; r++) {
        const float* egr = eg + r * ES;
        const float* rgr = rg + r * ES;
        float pa = 0.f;
#pragma unroll
        for (int j = lane; j < H; j += 32) {
            float ev = egr[j] + g_C[0][j];
            float rv = rgr[j] + g_C[1][j];
            pa += tanhf(ev + rv) * attnW[j];
        }
#pragma unroll
        for (int o = 16; o; o >>= 1) pa += __shfl_xor_sync(0xffffffffu, pa, o);
        float attn = 1.f / (1.f + expf(-(pa + attnb_v)));
        float q = 0.f;
#pragma unroll
        for (int j = lane; j < H; j += 32) {
            float ev = egr[j] + g_C[0][j];
            float rv = rgr[j] + g_C[1][j];
            float f = attn * ev + (1.f - attn) * rv;
            q += fmaxf(f, 0.f) * fc2W[j];
        }
#pragma unroll
        for (int o = 16; o; o >>= 1) q += __shfl_xor_sync(0xffffffffu, q, o);
        if (lane == 0) out[rb + r] = 1.f / (1.f + expf(-(q + fc2b_v)));
    }
}

// ---------------- launch ----------------
extern "C" void kernel_launch(void* const* d_in, const int* in_sizes, int n_in,
                              void* d_out, int out_size) {
    const float* ecc = (const float*)d_in[0];
    const float* err = (const float*)d_in[1];
    const float* conv_ecc_w = (const float*)d_in[2];
    const float* conv_ecc_b = (const float*)d_in[3];
    const float* conv_err_w = (const float*)d_in[4];
    const float* conv_err_b = (const float*)d_in[5];
    const float* cheb_ecc_W = (const float*)d_in[6];
    const float* cheb_ecc_b = (const float*)d_in[7];
    const float* cheb_err_W = (const float*)d_in[8];
    const float* cheb_err_b = (const float*)d_in[9];
    const float* ecc_proj_W = (const float*)d_in[10];
    const float* ecc_proj_b = (const float*)d_in[11];
    const float* err_proj_W = (const float*)d_in[12];
    const float* err_proj_b = (const float*)d_in[13];
    const float* attn_W = (const float*)d_in[14];
    const float* attn_b = (const float*)d_in[15];
    const float* fc2_W = (const float*)d_in[16];
    const float* fc2_b = (const float*)d_in[17];
    const int* ei_ecc = (const int*)d_in[18];
    const int* ei_err = (const int*)d_in[19];
    const int Ee = in_sizes[18] / 2;
    const int Er = in_sizes[19] / 2;

    k_pre2<<<(VE + VR) * 4 + 17, 256>>>(
        ecc_proj_W, err_proj_W, ecc_proj_b, err_proj_b,
        cheb_ecc_b, cheb_err_b,
        conv_ecc_w, conv_ecc_b, conv_err_w, conv_err_b,
        cheb_ecc_W, cheb_err_W, ei_ecc, Ee, ei_err, Er);

    cudaFuncSetAttribute(k_main, cudaFuncAttributeMaxDynamicSharedMemorySize,
                         SM_MAIN);
    k_main<<<BATCH / MT, NTHR, SM_MAIN>>>(ecc, err, attn_W, attn_b,
                                          fc2_W, fc2_b, (float*)d_out);
}

// round 17
// speedup vs baseline: 1.2010x; 1.2010x over previous
#include <cuda_runtime.h>
#include <cuda_fp16.h>
#include <math.h>
#include <stdint.h>

#define BATCH 4096
#define T 25
#define CT 32
#define FIN 800
#define GO 64
#define H 256
#define VE 16
#define VR 12
#define KE 400
#define KR 300
#define NCHE 7            /* ecc chunks of 64 */
#define NCHR 5            /* err chunks of 64 */
#define NCH 12
#define NPH 6             /* phases: 2 chunks each */
#define KC 64
#define MT 32
#define NTHR 512
#define RSB 144           /* staged row stride, bytes */
#define ES 260
#define NTASK 104
#define CHB 36864         /* bytes per staged B chunk: 256*144 */
#define XCHB 4608         /* bytes per staged X chunk: 32*144 */

#define XF_OFS 0
#define BF_OFS 9216       /* after 2 X chunk slots */
#define BUFSZ 82944       /* 9216 + 2*36864 */
#define SM_MAIN (2 * BUFSZ)   /* 165888 */

// ---------------- device scratch ----------------
__device__ float g_U[4][T * GO];
__device__ float g_S[4][GO];
__device__ int   g_ctr;
__device__ __align__(16) __half g_Bs[NCH * CHB / 2];   // staged-layout B images
__device__ float g_C[2][H];

// ---------------- helpers ----------------
__device__ __forceinline__ void mma16816(float* d, uint32_t a0, uint32_t a1,
                                         uint32_t a2, uint32_t a3,
                                         uint32_t b0, uint32_t b1) {
    asm volatile(
        "mma.sync.aligned.m16n8k16.row.col.f32.f16.f16.f32 "
        "{%0,%1,%2,%3}, {%4,%5,%6,%7}, {%8,%9}, {%0,%1,%2,%3};"
        : "+f"(d[0]), "+f"(d[1]), "+f"(d[2]), "+f"(d[3])
        : "r"(a0), "r"(a1), "r"(a2), "r"(a3), "r"(b0), "r"(b1));
}
__device__ __forceinline__ void ldsm4(uint32_t* r, uint32_t addr) {
    asm volatile(
        "ldmatrix.sync.aligned.m8n8.x4.shared.b16 {%0,%1,%2,%3}, [%4];"
        : "=r"(r[0]), "=r"(r[1]), "=r"(r[2]), "=r"(r[3])
        : "r"(addr));
}
__device__ __forceinline__ uint32_t pack_h2(__half lo, __half hi) {
    return ((uint32_t)__half_as_ushort(hi) << 16) |
           (uint32_t)__half_as_ushort(lo);
}
__device__ __forceinline__ uint32_t smem_u32(const void* p) {
    uint32_t a;
    asm("{ .reg .u64 t; cvta.to.shared.u64 t, %1; cvt.u32.u64 %0, t; }"
        : "=r"(a) : "l"(p));
    return a;
}
__device__ __forceinline__ void cpa16(uint32_t dst, const void* src) {
    asm volatile("cp.async.cg.shared.global [%0], [%1], 16;"
                 :: "r"(dst), "l"(src));
}

// ===== fused precompute: U/S tasks + spin-sync + staged B + C (R14) =====
__global__ void __launch_bounds__(256) k_pre2(
    const float* __restrict__ Pe, const float* __restrict__ Pr,
    const float* __restrict__ pbe, const float* __restrict__ pbr,
    const float* __restrict__ chbe, const float* __restrict__ chbr,
    const float* __restrict__ cwe, const float* __restrict__ cbe,
    const float* __restrict__ cwr, const float* __restrict__ cbr,
    const float* __restrict__ Wche, const float* __restrict__ Wchr,
    const int* __restrict__ eie, int Ee, const int* __restrict__ eir, int Er) {
    __shared__ float sP[64 * 64];
    __shared__ float sQ[64 * 64];
    __shared__ float sU0[T * GO];
    __shared__ float sU1[T * GO];
    __shared__ float swe[64];
    __shared__ float sws[16];
    const int tid = threadIdx.x;
    const int b = blockIdx.x;
    const int o = tid & 63;
    const int cc = tid >> 6;
    float* red = sQ;

    if (b < 100) {
        const int mat = b / T, tp = b % T;
        const int branch = mat >> 1, which = mat & 1;
        const float* cw = branch ? cwr : cwe;
        const float* W = (branch ? Wchr : Wche) + which * FIN * GO;
        float acc = 0.f;
#pragma unroll
        for (int k = 0; k < 3; k++) {
            int t = tp - k + 1;
            if (t >= 0 && t < T) {
#pragma unroll
                for (int cj = 0; cj < 8; cj++) {
                    int c = cc * 8 + cj;
                    acc += cw[c * 3 + k] * W[(c * T + t) * GO + o];
                }
            }
        }
        red[tid] = acc;
        __syncthreads();
        if (tid < 64)
            g_U[mat][tp * GO + tid] =
                red[tid] + red[64 + tid] + red[128 + tid] + red[192 + tid];
        __syncthreads();
        __threadfence();
        if (tid == 0) atomicAdd(&g_ctr, 1);
    } else if (b < 104) {
        const int mat = b - 100;
        const int branch = mat >> 1, which = mat & 1;
        const float* cb = branch ? cbr : cbe;
        const float* W = (branch ? Wchr : Wche) + which * FIN * GO;
        float acc = 0.f;
#pragma unroll
        for (int cj = 0; cj < 8; cj++) {
            int c = cc * 8 + cj;
            float s = 0.f;
#pragma unroll
            for (int t = 0; t < T; t++) s += W[(c * T + t) * GO + o];
            acc += cb[c] * s;
        }
        red[tid] = acc;
        __syncthreads();
        if (tid < 64)
            g_S[mat][tid] =
                red[tid] + red[64 + tid] + red[128 + tid] + red[192 + tid];
        __syncthreads();
        __threadfence();
        if (tid == 0) atomicAdd(&g_ctr, 1);
    }

    if (b < (VE + VR) * 4) {
        const int vb = b >> 2, hb = (b & 3) * 64;
        const int br = vb >= VE;
        const int v = br ? vb - VE : vb;
        const float* P = br ? Pr : Pe;
        const int* ei = br ? eir : eie;
        const int E = br ? Er : Ee;

        if (tid < E) {
            int s = ei[tid], d = ei[E + tid];
            int degs = 0, degd = 0;
            for (int i = 0; i < E; i++) {
                int si = ei[i];
                degs += (si == s);
                degd += (si == d);
            }
            float ds = degs > 0 ? rsqrtf((float)degs) : 0.f;
            float dd = degd > 0 ? rsqrtf((float)degd) : 0.f;
            swe[tid] = -ds * dd;
        }
        __syncthreads();
        int cnt = 0;
        int nd[4] = {0, 0, 0, 0};
        float nw[4] = {0.f, 0.f, 0.f, 0.f};
        for (int e = 0; e < E; e++) {
            if (ei[e] == v && cnt < 4) {
                nd[cnt] = ei[E + e];
                nw[cnt] = swe[e];
                cnt++;
            }
        }

        for (int i4 = tid; i4 < 1024; i4 += 256) {
            int oo = i4 >> 4, hl4 = (i4 & 15) * 4;
            ((float4*)sP)[i4] = *(const float4*)&P[(v * GO + oo) * H + hb + hl4];
            float4 q = make_float4(0.f, 0.f, 0.f, 0.f);
#pragma unroll
            for (int j = 0; j < 4; j++) {
                if (j < cnt) {
                    float4 pd = *(const float4*)&P[(nd[j] * GO + oo) * H + hb + hl4];
                    q.x += nw[j] * pd.x;
                    q.y += nw[j] * pd.y;
                    q.z += nw[j] * pd.z;
                    q.w += nw[j] * pd.w;
                }
            }
            ((float4*)sQ)[i4] = q;
        }

        if (tid == 0) {
            while (atomicAdd(&g_ctr, 0) < NTASK) {
            }
        }
        __syncthreads();
        __threadfence();
        {
            const float4* U0 = (const float4*)g_U[2 * br];
            const float4* U1 = (const float4*)g_U[2 * br + 1];
            for (int i = tid; i < T * GO / 4; i += 256) {
                ((float4*)sU0)[i] = U0[i];
                ((float4*)sU1)[i] = U1[i];
            }
        }
        __syncthreads();

        const int hl4 = (tid & 15) * 4;
        const int tpg = tid >> 4;
        for (int tp = tpg; tp < T; tp += 16) {
            float4 acc = make_float4(0.f, 0.f, 0.f, 0.f);
#pragma unroll 16
            for (int oo = 0; oo < 64; oo++) {
                float4 p = *(const float4*)&sP[oo * 64 + hl4];
                float4 q = *(const float4*)&sQ[oo * 64 + hl4];
                float u0 = sU0[tp * GO + oo];
                float u1 = sU1[tp * GO + oo];
                acc.x += u0 * p.x + u1 * q.x;
                acc.y += u0 * p.y + u1 * q.y;
                acc.z += u0 * p.z + u1 * q.z;
                acc.w += u0 * p.w + u1 * q.w;
            }
            const int kg = v * T + tp;
            const int chunkG = (br ? NCHE : 0) + (kg >> 6);
            const int col = kg & 63;
            float vals[4] = {acc.x, acc.y, acc.z, acc.w};
#pragma unroll
            for (int j = 0; j < 4; j++) {
                int n = hb + hl4 + j;
                g_Bs[chunkG * (CHB / 2) + n * (RSB / 2) + col] =
                    __float2half_rn(vals[j]);
            }
        }
    } else if (b < (VE + VR) * 4 + 16) {
        const int cb = b - (VE + VR) * 4;
        const int br = cb >> 3;
        const int hc = cb & 7;
        const float* chb = br ? chbr : chbe;
        const float* pb = br ? pbr : pbe;
        const float* P = br ? Pr : Pe;
        const int* ei = br ? eir : eie;
        const int E = br ? Er : Ee;
        const int V = br ? VR : VE;
        float* cfo = sP;
        float* s1v = sP + 64;
        float* red2 = sP + 160;

        if (tid < E) {
            int s = ei[tid], d = ei[E + tid];
            int degs = 0, degd = 0;
            for (int i = 0; i < E; i++) {
                int si = ei[i];
                degs += (si == s);
                degd += (si == d);
            }
            float ds = degs > 0 ? rsqrtf((float)degs) : 0.f;
            float dd = degd > 0 ? rsqrtf((float)degd) : 0.f;
            swe[tid] = -ds * dd;
        }
        __syncthreads();
        if (tid < 16) {
            float ws = 0.f;
            if (tid < V)
                for (int e = 0; e < E; e++)
                    if (ei[E + e] == tid) ws += swe[e];
            sws[tid] = ws;
        }

        if (tid == 0) {
            while (atomicAdd(&g_ctr, 0) < NTASK) {
            }
        }
        __syncthreads();
        __threadfence();
        if (tid < 64) {
            cfo[tid] = chb[tid] + g_S[2 * br][tid];
            s1v[tid] = g_S[2 * br + 1][tid];
        }
        __syncthreads();

        const int lane = tid & 31, rp = tid >> 5;
        const int h = hc * 32 + lane;
        const int R = V * GO;
        const int RP = R >> 3;
        float acc = 0.f;
#pragma unroll 4
        for (int r = rp * RP; r < (rp + 1) * RP; r++) {
            int oo = r & 63, v = r >> 6;
            float coef = cfo[oo] + s1v[oo] * sws[v];
            acc += coef * P[r * H + h];
        }
        red2[tid] = acc;
        __syncthreads();
        if (tid < 32) {
            float s = pb[h];
#pragma unroll
            for (int j = 0; j < 8; j++) s += red2[j * 32 + lane];
            g_C[br][h] = s;
        }
    } else {
        // zero-fill K padding: ecc chunk 6 cols [16,64); err chunk 11 cols [44,64)
        const int NE = 256 * 48;
        const int NR = 256 * 20;
        __half z = __float2half_rn(0.f);
        for (int i = tid; i < NE + NR; i += 256) {
            int chunkG, n, col;
            if (i < NE) {
                chunkG = 6;
                n = i / 48;
                col = 16 + i % 48;
            } else {
                int r = i - NE;
                chunkG = 11;
                n = r / 20;
                col = 44 + r % 20;
            }
            g_Bs[chunkG * (CHB / 2) + n * (RSB / 2) + col] = z;
        }
    }
}

// ------- main: double-buffered cp.async B staging, fat phases, ldsm mma -------
extern __shared__ char smx[];

__global__ void __launch_bounds__(NTHR, 1)
k_main(const float* __restrict__ ecc, const float* __restrict__ err,
       const float* __restrict__ attnW, const float* __restrict__ attnb,
       const float* __restrict__ fc2W, const float* __restrict__ fc2b,
       float* __restrict__ out) {
    const int tid = threadIdx.x;
    const int wid = tid >> 5;
    const int lane = tid & 31;
    const int g = lane >> 2;
    const int i2 = (lane & 3) * 2;
    const int ns = wid * 16;
    const int rb = blockIdx.x * MT;

    const uint32_t su = smem_u32(smx);
    const uint32_t arow = (uint32_t)(((lane & 7) + (lane & 8)) * RSB +
                                     (lane >> 4) * 16);
    const uint32_t brow = (uint32_t)((lane & 7) * RSB + (lane >> 3) * 16);

    if (blockIdx.x == 0 && tid == 0) g_ctr = 0;

    float de[2][2][4], dr[2][2][4];
#pragma unroll
    for (int mt = 0; mt < 2; mt++)
#pragma unroll
        for (int nt = 0; nt < 2; nt++)
#pragma unroll
            for (int j = 0; j < 4; j++) {
                de[mt][nt][j] = 0.f;
                dr[mt][nt][j] = 0.f;
            }

    const int xrow = tid >> 4;
    const int xkq = tid & 15;
    const int xsoff = xrow * RSB + xkq * 8;

    // ---- stage helper (X manual fp16 convert, B via cp.async) ----
    auto stage = [&](int p, int s) {
        char* buf = smx + s * BUFSZ;
        const uint32_t bufu = su + (uint32_t)(s * BUFSZ);
#pragma unroll
        for (int j = 0; j < 2; j++) {
            const int chunk = 2 * p + j;
            const int br = (chunk >= NCHE);
            const int cc = br ? chunk - NCHE : chunk;
            const float* X = br ? err : ecc;
            const int Kreal = br ? KR : KE;
            int k = cc * KC + xkq * 4;
            float4 x = make_float4(0.f, 0.f, 0.f, 0.f);
            if (k < Kreal)
                x = *(const float4*)&X[(size_t)(rb + xrow) * Kreal + k];
            *(uint2*)(buf + XF_OFS + j * XCHB + xsoff) =
                make_uint2(pack_h2(__float2half_rn(x.x), __float2half_rn(x.y)),
                           pack_h2(__float2half_rn(x.z), __float2half_rn(x.w)));
        }
        const char* src = (const char*)g_Bs + p * (2 * CHB);
        int off = tid * 16;
#pragma unroll
        for (int it = 0; it < 9; it++) {
            cpa16(bufu + BF_OFS + off, src + off);
            off += NTHR * 16;
        }
        asm volatile("cp.async.commit_group;" ::: "memory");
    };

    stage(0, 0);
#pragma unroll 1
    for (int p = 0; p < NPH; p++) {
        const int s = p & 1;
        asm volatile("cp.async.wait_group 0;" ::: "memory");
        __syncthreads();   // staged data visible; prev buf mma finished
        if (p + 1 < NPH) stage(p + 1, s ^ 1);

        const uint32_t bufu = su + (uint32_t)(s * BUFSZ);
#pragma unroll
        for (int j = 0; j < 2; j++) {
            const int chunk = 2 * p + j;
            float (*d)[2][4] = (chunk >= NCHE) ? dr : de;
            const uint32_t bbase = bufu + BF_OFS + (uint32_t)(j * CHB) + brow;
            const uint32_t abase = bufu + XF_OFS + (uint32_t)(j * XCHB) + arow;
            uint32_t bf[2][2][4];
#pragma unroll
            for (int nt = 0; nt < 2; nt++)
#pragma unroll
                for (int h = 0; h < 2; h++)
                    ldsm4(bf[nt][h],
                          bbase + (uint32_t)((ns + nt * 8) * RSB + h * 64));
#pragma unroll
            for (int ks = 0; ks < 4; ks++) {
                uint32_t aa[2][4];
                ldsm4(aa[0], abase + (uint32_t)(ks * 32));
                ldsm4(aa[1], abase + (uint32_t)(16 * RSB + ks * 32));
                const int h = ks >> 1, q = (ks & 1) * 2;
#pragma unroll
                for (int nt = 0; nt < 2; nt++) {
                    uint32_t b0 = bf[nt][h][q];
                    uint32_t b1 = bf[nt][h][q + 1];
#pragma unroll
                    for (int mt = 0; mt < 2; mt++)
                        mma16816(d[mt][nt], aa[mt][0], aa[mt][1], aa[mt][2],
                                 aa[mt][3], b0, b1);
                }
            }
        }
        __syncthreads();   // mma reads done before this buf is restaged
    }

    // -------- write fragments to smem (reuse staging buffer) --------
    float* eg = (float*)smx;
    float* rg = eg + MT * ES;
#pragma unroll
    for (int mt = 0; mt < 2; mt++)
#pragma unroll
        for (int nt = 0; nt < 2; nt++) {
            int row = mt * 16 + g;
            int col = ns + nt * 8 + i2;
            eg[row * ES + col] = de[mt][nt][0];
            eg[row * ES + col + 1] = de[mt][nt][1];
            eg[(row + 8) * ES + col] = de[mt][nt][2];
            eg[(row + 8) * ES + col + 1] = de[mt][nt][3];
            rg[row * ES + col] = dr[mt][nt][0];
            rg[row * ES + col + 1] = dr[mt][nt][1];
            rg[(row + 8) * ES + col] = dr[mt][nt][2];
            rg[(row + 8) * ES + col + 1] = dr[mt][nt][3];
        }
    __syncthreads();

    // -------- gated tail: 1 warp per 2 rows --------
    const float attnb_v = attnb[0];
    const float fc2b_v = fc2b[0];
    for (int r = wid * 2; r < wid * 2 + 2; r++) {
        const float* egr = eg + r * ES;
        const float* rgr = rg + r * ES;
        float pa = 0.f;
#pragma unroll
        for (int j = lane; j < H; j += 32) {
            float ev = egr[j] + g_C[0][j];
            float rv = rgr[j] + g_C[1][j];
            pa += tanhf(ev + rv) * attnW[j];
        }
#pragma unroll
        for (int o = 16; o; o >>= 1) pa += __shfl_xor_sync(0xffffffffu, pa, o);
        float attn = 1.f / (1.f + expf(-(pa + attnb_v)));
        float q = 0.f;
#pragma unroll
        for (int j = lane; j < H; j += 32) {
            float ev = egr[j] + g_C[0][j];
            float rv = rgr[j] + g_C[1][j];
            float f = attn * ev + (1.f - attn) * rv;
            q += fmaxf(f, 0.f) * fc2W[j];
        }
#pragma unroll
        for (int o = 16; o; o >>= 1) q += __shfl_xor_sync(0xffffffffu, q, o);
        if (lane == 0) out[rb + r] = 1.f / (1.f + expf(-(q + fc2b_v)));
    }
}

// ---------------- launch ----------------
extern "C" void kernel_launch(void* const* d_in, const int* in_sizes, int n_in,
                              void* d_out, int out_size) {
    const float* ecc = (const float*)d_in[0];
    const float* err = (const float*)d_in[1];
    const float* conv_ecc_w = (const float*)d_in[2];
    const float* conv_ecc_b = (const float*)d_in[3];
    const float* conv_err_w = (const float*)d_in[4];
    const float* conv_err_b = (const float*)d_in[5];
    const float* cheb_ecc_W = (const float*)d_in[6];
    const float* cheb_ecc_b = (const float*)d_in[7];
    const float* cheb_err_W = (const float*)d_in[8];
    const float* cheb_err_b = (const float*)d_in[9];
    const float* ecc_proj_W = (const float*)d_in[10];
    const float* ecc_proj_b = (const float*)d_in[11];
    const float* err_proj_W = (const float*)d_in[12];
    const float* err_proj_b = (const float*)d_in[13];
    const float* attn_W = (const float*)d_in[14];
    const float* attn_b = (const float*)d_in[15];
    const float* fc2_W = (const float*)d_in[16];
    const float* fc2_b = (const float*)d_in[17];
    const int* ei_ecc = (const int*)d_in[18];
    const int* ei_err = (const int*)d_in[19];
    const int Ee = in_sizes[18] / 2;
    const int Er = in_sizes[19] / 2;

    k_pre2<<<(VE + VR) * 4 + 17, 256>>>(
        ecc_proj_W, err_proj_W, ecc_proj_b, err_proj_b,
        cheb_ecc_b, cheb_err_b,
        conv_ecc_w, conv_ecc_b, conv_err_w, conv_err_b,
        cheb_ecc_W, cheb_err_W, ei_ecc, Ee, ei_err, Er);

    cudaFuncSetAttribute(k_main, cudaFuncAttributeMaxDynamicSharedMemorySize,
                         SM_MAIN);
    k_main<<<BATCH / MT, NTHR, SM_MAIN>>>(ecc, err, attn_W, attn_b,
                                          fc2_W, fc2_b, (float*)d_out);
}